// round 6
// baseline (speedup 1.0000x reference)
#include <cuda_runtime.h>
#include <cstdint>
#include <cstddef>

#define D_FEAT    128
#define N_STEPS   256          // O_SIZE: only first 256 scan steps feed the output
#define N_NEURONS 1024
#define W_TILE    (D_FEAT * D_FEAT)           // 16384 floats = 64 KB per step
#define W_HALF    (W_TILE / 2)                // 8192 floats = 32 KB (rows 64..127)
#define NBUF      3

// smem layout (floats): Wbuf[3] x 32KB | vbuf 128 | part 1024 | acoef 256 | mbars(3x8B)
#define SMF_VBUF    (NBUF * W_HALF)
#define SMF_PART    (SMF_VBUF + 128)
#define SMF_ACOEF   (SMF_PART + 1024)
#define SMF_MBAR    (SMF_ACOEF + 256)         // float index; *4 is 8B-aligned
#define SMEM_FLOATS (SMF_MBAR + 8)
#define SMEM_BYTES  (SMEM_FLOATS * 4)

// Scratch: u_t vectors produced by the chain, consumed by the output kernel.
__device__ __align__(16) float g_u[N_STEPS * D_FEAT];

// ---------------- PTX helpers ----------------
__device__ __forceinline__ unsigned smem_u32(const void* p) {
    unsigned r;
    asm("{ .reg .u64 t; cvta.to.shared.u64 t, %1; cvt.u32.u64 %0, t; }" : "=r"(r) : "l"(p));
    return r;
}
__device__ __forceinline__ void mbar_init(unsigned m, unsigned cnt) {
    asm volatile("mbarrier.init.shared.b64 [%0], %1;" :: "r"(m), "r"(cnt) : "memory");
}
__device__ __forceinline__ void mbar_expect_tx(unsigned m, unsigned bytes) {
    asm volatile("mbarrier.arrive.expect_tx.shared.b64 _, [%0], %1;" :: "r"(m), "r"(bytes) : "memory");
}
__device__ __forceinline__ void mbar_wait(unsigned m, unsigned parity) {
    asm volatile(
        "{\n\t"
        ".reg .pred P1;\n\t"
        "WL_%=:\n\t"
        "mbarrier.try_wait.parity.acquire.cta.shared::cta.b64 P1, [%0], %1, 0x989680;\n\t"
        "@P1 bra.uni WD_%=;\n\t"
        "bra.uni WL_%=;\n\t"
        "WD_%=:\n\t"
        "}"
        :: "r"(m), "r"(parity) : "memory");
}
__device__ __forceinline__ void tma_1d(unsigned dst, const void* src, unsigned bytes, unsigned m) {
    asm volatile(
        "cp.async.bulk.shared::cta.global.mbarrier::complete_tx::bytes [%0], [%1], %2, [%3];"
        :: "r"(dst), "l"(src), "r"(bytes), "r"(m) : "memory");
}
__device__ __forceinline__ float tanha(float v) {
    float r;
    asm("tanh.approx.f32 %0, %1;" : "=f"(r) : "f"(v));
    return r;
}

// One chain step, dual-port W streaming.
//   rows 0..63  : registers RC (LDG.128 pipeline, issued one step ahead into RN)
//   rows 64..127: smem ring buf (TMA), read via LDS.128
#define CHAIN_STEP(RC, RN, t) do {                                                   \
    if ((t) < N_STEPS - 1) {                                                         \
        const float4* Wn = (const float4*)W + (size_t)((t) + 1) * 4096 + thr_off;    \
        _Pragma("unroll")                                                            \
        for (int r = 0; r < 8; r++) RN[r] = __ldcs(Wn + (r << 8));                   \
    }                                                                                \
    const int      buf_ = (t) % NBUF;                                                \
    const unsigned mb_  = mbar_base + 8u * buf_;                                     \
    mbar_wait(mb_, ((t) / NBUF) & 1);                                                \
    const float4* W4s = (const float4*)(sm + buf_ * W_HALF);                         \
    float4 acc = make_float4(0.f, 0.f, 0.f, 0.f);                                    \
    _Pragma("unroll")                                                                \
    for (int r = 0; r < 8; r++) {                                                    \
        const int lr = (r << 3) + w;                   /* 0..63 */                   \
        const float vj  = vbuf[lr];                    /* register half row */       \
        acc.x += vj * RC[r].x; acc.y += vj * RC[r].y;                                \
        acc.z += vj * RC[r].z; acc.w += vj * RC[r].w;                                \
        const float vj2 = vbuf[64 + lr];               /* smem half row */           \
        const float4 wv = W4s[(lr << 5) + lane];       /* conflict-free LDS.128 */   \
        acc.x += vj2 * wv.x; acc.y += vj2 * wv.y;                                    \
        acc.z += vj2 * wv.z; acc.w += vj2 * wv.w;                                    \
    }                                                                                \
    ((float4*)part)[(w << 5) + lane] = acc;                                          \
    __syncthreads();                                   /* smem buf reads done */     \
    if (tid == 0 && (t) + NBUF < N_STEPS) {                                          \
        mbar_expect_tx(mb_, W_HALF * 4);                                             \
        tma_1d(smem_u32(sm + buf_ * W_HALF),                                         \
               W + (size_t)((t) + NBUF) * W_TILE + W_HALF, W_HALF * 4, mb_);         \
    }                                                                                \
    if (tid < 128) {                                                                 \
        float u = part[tid]       + part[128 + tid] + part[256 + tid]                \
                + part[384 + tid] + part[512 + tid] + part[640 + tid]                \
                + part[768 + tid] + part[896 + tid];                                 \
        __stcg(&g_u[(t) * 128 + tid], u);                                            \
        if ((t) < N_STEPS - 1) vbuf[tid] = tanhf(acoef[t] * u);                      \
    }                                                                                \
    __syncthreads();                                                                 \
} while (0)

// ---------------- Phase A: sequential chain (single CTA) ----------------
__global__ void __launch_bounds__(256, 1) chain_kernel(
    const float* __restrict__ x,         // (256,128)
    const float* __restrict__ pos_head,  // (1024,64) — only row 0 used
    const float* __restrict__ pos_tail,  // (1024,64) — only rows [0,256) used
    const float* __restrict__ W,         // (768,128,128) — only [0,256) used
    const float* __restrict__ a)         // (768,1024)
{
    extern __shared__ float sm[];
    float* vbuf  = sm + SMF_VBUF;
    float* part  = sm + SMF_PART;
    float* acoef = sm + SMF_ACOEF;
    const unsigned mbar_base = smem_u32(sm + SMF_MBAR);

    const int tid  = threadIdx.x;
    const int w    = tid >> 5;
    const int lane = tid & 31;
    const int thr_off = (w << 5) + lane;   // float4 offset: row (r*8+w), chunk lane

    // ---- setup: v_0 + a-coefficient preload (off the serial path) ----
    {
        const int jcol = tid & 127, h = tid >> 7;
        float s = 0.f;
        const float* xp = x + (size_t)(h * 128) * D_FEAT + jcol;
        #pragma unroll 8
        for (int i = 0; i < 128; i++) s += xp[(size_t)i * D_FEAT];
        part[tid] = s;

        if (tid < N_STEPS - 1) acoef[tid] = __ldg(a + (size_t)tid * N_NEURONS + (tid + 1));
        __syncthreads();

        const int d = tid & 63, q = tid >> 6;
        float sd = 0.f;
        const float* pp = pos_tail + (size_t)(q * 64) * 64 + d;
        #pragma unroll 8
        for (int r = 0; r < 64; r++) sd += pp[r * 64];
        part[256 + tid] = sd;
        __syncthreads();

        if (tid < 64) {
            float dv = part[256 + tid] + part[320 + tid] + part[384 + tid] + part[448 + tid];
            part[512 + tid] = dv * pos_head[tid];
        }
        __syncthreads();
        if (tid == 0) {
            float s0 = 0.f;
            #pragma unroll
            for (int dd = 0; dd < 64; dd++) s0 += part[512 + dd];
            part[576] = s0;
        }
        __syncthreads();
        if (tid < 128) vbuf[tid] = part[576] * (part[tid] + part[128 + tid]);
    }

    if (tid == 0) {
        #pragma unroll
        for (int b = 0; b < NBUF; b++) mbar_init(mbar_base + 8u * b, 1);
    }
    __syncthreads();   // publishes v_0 + mbarrier init before first TMA

    if (tid == 0) {    // preload smem halves (rows 64..127) of tiles 0..2
        #pragma unroll
        for (int b = 0; b < NBUF; b++) {
            mbar_expect_tx(mbar_base + 8u * b, W_HALF * 4);
            tma_1d(smem_u32(sm + b * W_HALF), W + (size_t)b * W_TILE + W_HALF,
                   W_HALF * 4, mbar_base + 8u * b);
        }
    }

    // ---- prologue: register half (rows 0..63) of tile 0 ----
    float4 RA[8], RB[8];
    {
        const float4* W0 = (const float4*)W + thr_off;
        #pragma unroll
        for (int r = 0; r < 8; r++) RA[r] = __ldcs(W0 + (r << 8));
    }

    // ---- main chain: 256 steps, register double-buffered ----
    for (int t = 0; t < N_STEPS; t += 2) {
        CHAIN_STEP(RA, RB, t);
        CHAIN_STEP(RB, RA, t + 1);
    }
}

// ---------------- Phase B: output generation (full chip, DRAM-write bound) ----------------
__global__ void __launch_bounds__(256) out_kernel(const float* __restrict__ a,
                                                  float* __restrict__ out)
{
    __shared__ float4 us[32];
    __shared__ float as[128];
    const int t  = blockIdx.x >> 3;
    const int lb = blockIdx.x & 7;
    const int tid = threadIdx.x;

    if (tid < 32) us[tid] = __ldcg((const float4*)g_u + t * 32 + tid);
    if (tid >= 128) as[tid - 128] = __ldg(a + (size_t)t * N_NEURONS + lb * 128 + (tid - 128));
    __syncthreads();

    const int w = tid >> 5, lane = tid & 31;
    const float4 u4 = us[lane];                       // lane's 4 j-columns, reused 16x
    float4* op = (float4*)out + ((size_t)t * N_NEURONS + (size_t)lb * 128) * 32 + lane;

    #pragma unroll
    for (int it = 0; it < 16; it++) {
        const int l = (it << 3) + w;
        const float av = as[l];                       // warp-uniform smem broadcast
        float4 r;
        r.x = tanha(av * u4.x);
        r.y = tanha(av * u4.y);
        r.z = tanha(av * u4.z);
        r.w = tanha(av * u4.w);
        __stcs(op + (size_t)l * 32, r);               // streaming store, 512B/warp coalesced
    }
}

// ---------------- launch ----------------
extern "C" void kernel_launch(void* const* d_in, const int* in_sizes, int n_in,
                              void* d_out, int out_size) {
    const float* x  = (const float*)d_in[0];
    const float* ph = (const float*)d_in[1];
    const float* pt = (const float*)d_in[2];
    const float* W  = (const float*)d_in[3];
    const float* a  = (const float*)d_in[4];

    cudaFuncSetAttribute(chain_kernel, cudaFuncAttributeMaxDynamicSharedMemorySize, SMEM_BYTES);
    chain_kernel<<<1, 256, SMEM_BYTES>>>(x, ph, pt, W, a);
    out_kernel<<<N_STEPS * 8, 256>>>(a, (float*)d_out);
}

// round 8
// speedup vs baseline: 1.1501x; 1.1501x over previous
#include <cuda_runtime.h>
#include <cstdint>
#include <cstddef>

#define D_FEAT    128
#define N_STEPS   256
#define N_NEURONS 1024
#define W_TILE    (D_FEAT * D_FEAT)    // 16384 floats = 64 KB per step
#define W_SLICE   8192                 // 32 KB: one CTA's (k=128) x (jloc=64) slice
#define NBUF      3

// smem (floats): Wring[3*8192] | vb[2*128] | part 640 | acoef 256 | bars
#define SMF_VB     24576
#define SMF_PART   24832
#define SMF_ACOEF  25472
#define SMF_BAR    25728               // *4 = 102912, 8B aligned
#define SMEM_FLOATS 25744
#define SMEM_BYTES  (SMEM_FLOATS * 4)

// Scratch: repacked W (16 MB) + u vectors.
__device__ __align__(16) float g_W2[N_STEPS * W_TILE];
__device__ __align__(16) float g_u[N_STEPS * D_FEAT];

// ---------------- PTX helpers ----------------
__device__ __forceinline__ unsigned smem_u32(const void* p) {
    unsigned r;
    asm("{ .reg .u64 t; cvta.to.shared.u64 t, %1; cvt.u32.u64 %0, t; }" : "=r"(r) : "l"(p));
    return r;
}
__device__ __forceinline__ void mbar_init(unsigned m, unsigned cnt) {
    asm volatile("mbarrier.init.shared.b64 [%0], %1;" :: "r"(m), "r"(cnt) : "memory");
}
__device__ __forceinline__ void mbar_expect_tx(unsigned m, unsigned bytes) {
    asm volatile("mbarrier.arrive.expect_tx.shared.b64 _, [%0], %1;" :: "r"(m), "r"(bytes) : "memory");
}
__device__ __forceinline__ void mbar_wait(unsigned m, unsigned parity) {
    asm volatile(
        "{\n\t"
        ".reg .pred P1;\n\t"
        "WL_%=:\n\t"
        "mbarrier.try_wait.parity.acquire.cta.shared::cta.b64 P1, [%0], %1, 0x989680;\n\t"
        "@P1 bra.uni WD_%=;\n\t"
        "bra.uni WL_%=;\n\t"
        "WD_%=:\n\t"
        "}"
        :: "r"(m), "r"(parity) : "memory");
}
// cluster-scope acquire wait (peer DSMEM stores must be visible after this)
__device__ __forceinline__ void mbar_wait_cl(unsigned m, unsigned parity) {
    asm volatile(
        "{\n\t"
        ".reg .pred P1;\n\t"
        "WL_%=:\n\t"
        "mbarrier.try_wait.parity.acquire.cluster.shared::cta.b64 P1, [%0], %1, 0x989680;\n\t"
        "@P1 bra.uni WD_%=;\n\t"
        "bra.uni WL_%=;\n\t"
        "WD_%=:\n\t"
        "}"
        :: "r"(m), "r"(parity) : "memory");
}
__device__ __forceinline__ void tma_1d(unsigned dst, const void* src, unsigned bytes, unsigned m) {
    asm volatile(
        "cp.async.bulk.shared::cta.global.mbarrier::complete_tx::bytes [%0], [%1], %2, [%3];"
        :: "r"(dst), "l"(src), "r"(bytes), "r"(m) : "memory");
}
__device__ __forceinline__ unsigned mapa_u32(unsigned laddr, unsigned rank) {
    unsigned r;
    asm("mapa.shared::cluster.u32 %0, %1, %2;" : "=r"(r) : "r"(laddr), "r"(rank));
    return r;
}
__device__ __forceinline__ float tanha(float v) {
    float r;
    asm("tanh.approx.f32 %0, %1;" : "=f"(r) : "f"(v));
    return r;
}

// ---------------- repack: W[t][k][j] -> g_W2[(t*2+c)][k][jloc] (32 KB contiguous slices) ----
__global__ void __launch_bounds__(256) repack_kernel(const float* __restrict__ W) {
    const int b = blockIdx.x;            // 0..511 : t = b>>1, c = b&1
    const int t = b >> 1, c = b & 1;
    const float4* src = (const float4*)W;
    float4* dst = (float4*)g_W2 + (size_t)b * 2048;
    #pragma unroll
    for (int i = 0; i < 8; i++) {
        const int idx = i * 256 + threadIdx.x;   // 0..2047 float4s of the slice
        const int k = idx >> 4, j4 = idx & 15;
        dst[idx] = __ldcs(src + (size_t)t * 4096 + k * 32 + c * 16 + j4);
    }
}

// ---------------- Phase A: chain on a 2-CTA cluster ----------------
// CTA c owns j-columns [64c, 64c+64). Per step: read own 32KB W slice (TMA ring),
// u[j] = sum_k v[k]*W[k][j], v-half = tanh(acoef*u) computed locally, 256B v-half
// exchanged via DSMEM + mbarrier. Local v-half consumed first next step -> DSMEM
// latency off the critical path.
__global__ void __launch_bounds__(256, 1) __cluster_dims__(2, 1, 1) chain_kernel(
    const float* __restrict__ x,         // (256,128)
    const float* __restrict__ pos_head,  // (1024,64) — row 0
    const float* __restrict__ pos_tail,  // (1024,64) — rows [0,256)
    const float* __restrict__ a)         // (768,1024)
{
    extern __shared__ float sm[];
    float* vb    = sm + SMF_VB;     // [2][128]
    float* part  = sm + SMF_PART;   // 640
    float* acoef = sm + SMF_ACOEF;  // 256
    const unsigned bar_base = smem_u32(sm + SMF_BAR);   // wbar[3] then vbar[2]

    const int tid  = threadIdx.x;
    const int w    = tid >> 5;
    const int lane = tid & 31;
    unsigned rank; asm("mov.u32 %0, %%cluster_ctarank;" : "=r"(rank));
    const unsigned peer = rank ^ 1u;

    // ---- setup (both CTAs redundantly): v_0 full + acoef preload ----
    {
        const int jcol = tid & 127, h = tid >> 7;
        float s = 0.f;
        const float* xp = x + (size_t)(h * 128) * D_FEAT + jcol;
        #pragma unroll 8
        for (int i = 0; i < 128; i++) s += xp[(size_t)i * D_FEAT];
        part[tid] = s;

        if (tid < N_STEPS - 1) acoef[tid] = __ldg(a + (size_t)tid * N_NEURONS + (tid + 1));
        __syncthreads();

        const int d = tid & 63, q = tid >> 6;
        float sd = 0.f;
        const float* pp = pos_tail + (size_t)(q * 64) * 64 + d;
        #pragma unroll 8
        for (int r = 0; r < 64; r++) sd += pp[r * 64];
        part[256 + tid] = sd;
        __syncthreads();

        if (tid < 64) {
            float dv = part[256 + tid] + part[320 + tid] + part[384 + tid] + part[448 + tid];
            part[512 + tid] = dv * pos_head[tid];
        }
        __syncthreads();
        if (tid == 0) {
            float s0 = 0.f;
            #pragma unroll
            for (int dd = 0; dd < 64; dd++) s0 += part[512 + dd];
            part[576] = s0;
        }
        __syncthreads();
        if (tid < 128) vb[tid] = part[576] * (part[tid] + part[128 + tid]);  // vb[0][*]
    }

    if (tid == 0) {
        #pragma unroll
        for (int b = 0; b < NBUF; b++) mbar_init(bar_base + 8u * b, 1);
        mbar_init(bar_base + 24u, 64);        // vbar[0]: 64 remote arrives
        mbar_init(bar_base + 32u, 64);        // vbar[1]
    }
    __syncthreads();
    // All barriers initialized in BOTH CTAs before any remote arrive can land.
    asm volatile("barrier.cluster.arrive.aligned;" ::: "memory");
    asm volatile("barrier.cluster.wait.aligned;"   ::: "memory");

    if (tid == 0) {
        #pragma unroll
        for (int b = 0; b < NBUF; b++) {
            mbar_expect_tx(bar_base + 8u * b, W_SLICE * 4);
            tma_1d(smem_u32(sm + b * W_SLICE), g_W2 + (size_t)(b * 2 + rank) * W_SLICE,
                   W_SLICE * 4, bar_base + 8u * b);
        }
    }

    const int loc0 = rank * 64;         // my k-range for local-first consumption == my j-range
    const int pee0 = peer * 64;

    for (int t = 0; t < N_STEPS; t++) {
        const int      buf = t % NBUF;
        const unsigned wmb = bar_base + 8u * buf;
        const int      p   = t & 1;
        mbar_wait(wmb, (t / NBUF) & 1);

        const float2* Wr = (const float2*)(sm + buf * W_SLICE);   // [k][jloc], 64 f/row

        // -- local-half k rows (v-half produced locally last step) --
        float2 acc = make_float2(0.f, 0.f);
        {
            const float2 vl = ((const float2*)(vb + p * 128 + loc0))[lane];   // LDS.64
            #pragma unroll
            for (int r = 0; r < 8; r++) {
                const int kh = w * 8 + r;                          // 0..63 within half
                const float vj = __shfl_sync(0xffffffffu, (r & 1) ? vl.y : vl.x, kh >> 1);
                const float2 wv = Wr[(loc0 + kh) * 32 + lane];
                acc.x += vj * wv.x; acc.y += vj * wv.y;
            }
        }
        // -- peer-half: wait for DSMEM-delivered v-half (t=0: from setup) --
        if (t > 0) {
            const unsigned parity = (unsigned)(((t - 2 + p) >> 1) & 1);
            mbar_wait_cl(bar_base + 24u + 8u * p, parity);
        }
        {
            const float2 vp = ((const float2*)(vb + p * 128 + pee0))[lane];
            #pragma unroll
            for (int r = 0; r < 8; r++) {
                const int kh = w * 8 + r;
                const float vj = __shfl_sync(0xffffffffu, (r & 1) ? vp.y : vp.x, kh >> 1);
                const float2 wv = Wr[(pee0 + kh) * 32 + lane];
                acc.x += vj * wv.x; acc.y += vj * wv.y;
            }
        }
        ((float2*)part)[(w << 5) + lane] = acc;     // part[w*64 + 2lane(+1)]
        __syncthreads();                            // W-slice reads complete

        if (tid == 0 && t + NBUF < N_STEPS) {       // refill ring for t+3
            mbar_expect_tx(wmb, W_SLICE * 4);
            tma_1d(smem_u32(sm + buf * W_SLICE),
                   g_W2 + (size_t)((t + NBUF) * 2 + rank) * W_SLICE, W_SLICE * 4, wmb);
        }

        if (tid < 64) {   // tail: reduce 8 warp partials for my j-half
            float u = part[tid]       + part[64 + tid]  + part[128 + tid] + part[192 + tid]
                    + part[256 + tid] + part[320 + tid] + part[384 + tid] + part[448 + tid];
            __stcg(&g_u[t * 128 + loc0 + tid], u);
            if (t < N_STEPS - 1) {
                const float vn = tanhf(acoef[t] * u);       // accurate: feeds forward
                const int p1 = (t + 1) & 1;
                vb[p1 * 128 + loc0 + tid] = vn;             // local copy
                // remote copy + release-arrive on peer's vbar[p1]
                const unsigned la = smem_u32(&vb[p1 * 128 + loc0 + tid]);
                const unsigned ra = mapa_u32(la, peer);
                asm volatile("st.shared::cluster.f32 [%0], %1;" :: "r"(ra), "f"(vn) : "memory");
                const unsigned rb = mapa_u32(bar_base + 24u + 8u * (unsigned)p1, peer);
                asm volatile("mbarrier.arrive.release.cluster.shared::cluster.b64 _, [%0];"
                             :: "r"(rb) : "memory");
            }
        }
        __syncthreads();
    }

    // No CTA may exit while peer stores could still target this CTA's smem.
    asm volatile("barrier.cluster.arrive.aligned;" ::: "memory");
    asm volatile("barrier.cluster.wait.aligned;"   ::: "memory");
}

// ---------------- Phase B: output generation (full chip, DRAM-write bound) ----------------
__global__ void __launch_bounds__(256) out_kernel(const float* __restrict__ a,
                                                  float* __restrict__ out)
{
    __shared__ float4 us[32];
    __shared__ float as[128];
    const int t  = blockIdx.x >> 3;
    const int lb = blockIdx.x & 7;
    const int tid = threadIdx.x;

    if (tid < 32) us[tid] = __ldcg((const float4*)g_u + t * 32 + tid);
    if (tid >= 128) as[tid - 128] = __ldg(a + (size_t)t * N_NEURONS + lb * 128 + (tid - 128));
    __syncthreads();

    const int w = tid >> 5, lane = tid & 31;
    const float4 u4 = us[lane];
    float4* op = (float4*)out + ((size_t)t * N_NEURONS + (size_t)lb * 128) * 32 + lane;

    #pragma unroll
    for (int it = 0; it < 16; it++) {
        const int l = (it << 3) + w;
        const float av = as[l];
        float4 r;
        r.x = tanha(av * u4.x);
        r.y = tanha(av * u4.y);
        r.z = tanha(av * u4.z);
        r.w = tanha(av * u4.w);
        __stcs(op + (size_t)l * 32, r);
    }
}

// ---------------- launch ----------------
extern "C" void kernel_launch(void* const* d_in, const int* in_sizes, int n_in,
                              void* d_out, int out_size) {
    const float* x  = (const float*)d_in[0];
    const float* ph = (const float*)d_in[1];
    const float* pt = (const float*)d_in[2];
    const float* W  = (const float*)d_in[3];
    const float* a  = (const float*)d_in[4];

    repack_kernel<<<N_STEPS * 2, 256>>>(W);
    cudaFuncSetAttribute(chain_kernel, cudaFuncAttributeMaxDynamicSharedMemorySize, SMEM_BYTES);
    chain_kernel<<<2, 256, SMEM_BYTES>>>(x, ph, pt, a);
    out_kernel<<<N_STEPS * 8, 256>>>(a, (float*)d_out);
}